// round 7
// baseline (speedup 1.0000x reference)
#include <cuda_runtime.h>
#include <cstdint>
#include <cstddef>

// Problem constants
#define B_ 128
#define T_ 1024
#define D_ 64
#define H_ 256
#define O_ 128

// Persistent-kernel tiling: 128 CTAs = 16 (M) x 8 (N); tile = 8 rows x 32 cols
#define NCTA 128
#define BM 8
#define BN 32
#define FPAD 32   // flag padding (ints) = 128B between CTA flags

// ---------------- device globals (static scratch; no runtime allocation) ----
__device__ float g_xp[(size_t)B_ * T_ * H_];   // Xp[t][b][n] = x@Wx1 + b1  (134 MB)
__device__ float g_h1[2][B_ * H_];             // double-buffered layer-1 state
__device__ float g_h2[2][B_ * H_];             // double-buffered layer-2 state
__device__ int   g_arrive[NCTA * FPAD];        // barrier flags (monotonic ticks)

// ---------------- packed f32x2 helpers (sm_103a FFMA2 path) ----------------
__device__ __forceinline__ void fma2(unsigned long long& acc,
                                     unsigned long long a,
                                     unsigned long long b) {
    asm("fma.rn.f32x2 %0, %1, %2, %0;" : "+l"(acc) : "l"(a), "l"(b));
}
__device__ __forceinline__ void add2(unsigned long long& acc, unsigned long long a) {
    asm("add.rn.f32x2 %0, %0, %1;" : "+l"(acc) : "l"(a));
}
__device__ __forceinline__ unsigned long long dup2(float v) {
    unsigned long long r;
    asm("mov.b64 %0, {%1, %1};" : "=l"(r) : "r"(__float_as_uint(v)));
    return r;
}
__device__ __forceinline__ float lo32(unsigned long long v) {
    return __uint_as_float((unsigned)(v & 0xffffffffull));
}
__device__ __forceinline__ float hi32(unsigned long long v) {
    return __uint_as_float((unsigned)(v >> 32));
}

// ---------------- grid barrier: release/acquire flags, no atomics ----------
__device__ __forceinline__ void grid_barrier(int bid, int tid, int tick) {
    __syncthreads();                       // all CTA threads done with their stores
    if (tid == 0) {
        __threadfence();                   // make this CTA's global writes visible
        asm volatile("st.release.gpu.global.b32 [%0], %1;"
                     :: "l"(&g_arrive[bid * FPAD]), "r"(tick) : "memory");
    }
    if (tid < NCTA) {                      // thread t polls CTA t's flag
        const int* p = &g_arrive[tid * FPAD];
        int v;
        do {
            asm volatile("ld.acquire.gpu.global.b32 %0, [%1];"
                         : "=r"(v) : "l"(p) : "memory");
        } while (v - tick < 0);
    }
    __syncthreads();                       // broadcast acquire to whole CTA
}

// ---------------- load state tile [8 rows, 256 cols] transposed into smem --
// hs layout: hs[k][m], k=0..255, m=0..7 (row stride 8 floats = 32B)
__device__ __forceinline__ void load_tile(float* hs, const float* hg, int m0, int tid) {
    int m  = tid & 7;
    int kq = tid >> 3;   // 0..31
#pragma unroll
    for (int r = 0; r < 2; r++) {
        int k = (kq + r * 32) << 2;
        float4 v = __ldcg((const float4*)(hg + (m0 + m) * H_ + k));  // .cg: bypass L1 (cross-SM data)
        hs[(k + 0) * 8 + m] = v.x;
        hs[(k + 1) * 8 + m] = v.y;
        hs[(k + 2) * 8 + m] = v.z;
        hs[(k + 3) * 8 + m] = v.w;
    }
}

// ---------------- per-warp GEMM partial: warp w owns k-chunk [32w,32w+32) ---
// acc[j] packs output rows (m=2j, m=2j+1) for column n = lane.
__device__ __forceinline__ void gemm_acc(const float* hs, const float* Ws,
                                         int w, int lane, unsigned long long acc[4]) {
    const float* hp = hs + (w << 5) * 8;
    const float* wp = Ws + (w << 5) * BN + lane;
#pragma unroll
    for (int kk = 0; kk < 32; kk++) {
        ulonglong2 pa = *(const ulonglong2*)(hp + kk * 8);      // (m0,m1),(m2,m3) broadcast
        ulonglong2 pb = *(const ulonglong2*)(hp + kk * 8 + 4);  // (m4,m5),(m6,m7) broadcast
        unsigned long long wd = dup2(wp[kk * BN]);              // splat W[k][n]
        fma2(acc[0], pa.x, wd);
        fma2(acc[1], pa.y, wd);
        fma2(acc[2], pb.x, wd);
        fma2(acc[3], pb.y, wd);
    }
}

__device__ __forceinline__ void store_red(unsigned long long* red, int w, int lane,
                                          const unsigned long long acc[4]) {
    ulonglong2* rw = (ulonglong2*)(red + (((w << 5) + lane) << 2));
    rw[0] = make_ulonglong2(acc[0], acc[1]);
    rw[1] = make_ulonglong2(acc[2], acc[3]);
}

// Reader mapping keeps a warp's 32 lanes on 256 contiguous bytes: conflict-free.
__device__ __forceinline__ unsigned long long reduce8(const unsigned long long* red,
                                                      int n_e, int p_e) {
    unsigned long long s = red[(n_e << 2) + p_e];
#pragma unroll
    for (int w2 = 1; w2 < 8; w2++)
        add2(s, red[(((w2 << 5) + n_e) << 2) + p_e]);
    return s;
}

// ============================================================================
// Kernel 1: Xp[t][b][:] = x[b][t][:] @ Wx1 + b1   (fully parallel over t)
// ============================================================================
__global__ void __launch_bounds__(256) xproj_kernel(const float* __restrict__ x,
                                                    const float* __restrict__ Wx1,
                                                    const float* __restrict__ b1) {
    extern __shared__ float sm[];
    float* W_s = sm;            // [64][256]  64KB
    float* x_s = sm + D_ * H_;  // [128][64]  32KB
    const int t = blockIdx.x;
    const int tid = threadIdx.x;

    for (int i = tid; i < D_ * H_; i += 256) W_s[i] = Wx1[i];
    for (int i = tid; i < B_ * D_; i += 256) {
        int b = i >> 6, d = i & 63;
        x_s[i] = x[((size_t)b * T_ + t) * D_ + d];
    }
    __syncthreads();

    float wr[D_];
#pragma unroll
    for (int d = 0; d < D_; d++) wr[d] = W_s[d * H_ + tid];
    const float bv = b1[tid];
    float* op = g_xp + (size_t)t * (B_ * H_) + tid;

    for (int b = 0; b < B_; b++) {
        const float4* xr = (const float4*)(x_s + b * D_);
        float a0 = bv, a1 = 0.f, a2 = 0.f, a3 = 0.f;
#pragma unroll
        for (int d4 = 0; d4 < 16; d4 += 4) {
            float4 v0 = xr[d4 + 0], v1 = xr[d4 + 1], v2 = xr[d4 + 2], v3 = xr[d4 + 3];
            a0 += v0.x * wr[4 * d4 + 0]  + v0.y * wr[4 * d4 + 1]
                + v0.z * wr[4 * d4 + 2]  + v0.w * wr[4 * d4 + 3];
            a1 += v1.x * wr[4 * d4 + 4]  + v1.y * wr[4 * d4 + 5]
                + v1.z * wr[4 * d4 + 6]  + v1.w * wr[4 * d4 + 7];
            a2 += v2.x * wr[4 * d4 + 8]  + v2.y * wr[4 * d4 + 9]
                + v2.z * wr[4 * d4 + 10] + v2.w * wr[4 * d4 + 11];
            a3 += v3.x * wr[4 * d4 + 12] + v3.y * wr[4 * d4 + 13]
                + v3.z * wr[4 * d4 + 14] + v3.w * wr[4 * d4 + 15];
        }
        op[(size_t)b * H_] = (a0 + a1) + (a2 + a3);
    }
}

// ============================================================================
// Kernel 2: persistent two-layer RNN scan, 128 co-resident CTAs
// ============================================================================
__global__ void __launch_bounds__(256) rnn_main_kernel(const float* __restrict__ Wh1,
                                                       const float* __restrict__ Wx2,
                                                       const float* __restrict__ Wh2,
                                                       const float* __restrict__ b2v) {
    extern __shared__ float smem[];
    float* Wh1_s = smem;              // [256][32] 32KB
    float* Wx2_s = smem + 8192;       // [256][32] 32KB
    float* Wh2_s = smem + 16384;      // [256][32] 32KB
    float* hA_s  = smem + 24576;      // [256][8]   8KB (transposed state tile)
    float* hB_s  = smem + 26624;      // [256][8]   8KB
    unsigned long long* red_s = (unsigned long long*)(smem + 28672);  // [8][32][4] 8KB

    const int bid = blockIdx.x;
    const int tid = threadIdx.x;
    const int w = tid >> 5, lane = tid & 31;
    const int mi = bid >> 3, ni = bid & 7;
    const int m0 = mi * BM, n0 = ni * BN;

    // Cache this CTA's weight-column slices once (weights never touched again)
    for (int i = tid; i < 256 * BN; i += 256) {
        int k = i >> 5, n = i & 31;
        int gi = k * H_ + n0 + n;
        Wh1_s[i] = Wh1[gi];
        Wx2_s[i] = Wx2[gi];
        Wh2_s[i] = Wh2[gi];
    }
    // Zero-init parity-0 states (each CTA zeros its own tile)
    {
        int m = tid >> 5, n = tid & 31;  // 8x32 = 256 threads, one elem each
        g_h1[0][(m0 + m) * H_ + n0 + n] = 0.f;
        g_h2[0][(m0 + m) * H_ + n0 + n] = 0.f;
    }

    // Launch-relative tick base: flags are never reset, every launch starts
    // from the (uniform) value left by the previous launch -> deterministic.
    int tick = g_arrive[bid * FPAD];

    // Epilogue thread mapping (tid < 128): output (rows m0+2p_e,m0+2p_e+1, col n0+n_e)
    const int n_e = tid >> 2;
    const int p_e = tid & 3;
    const int r_off = (m0 + 2 * p_e) * H_ + n0 + n_e;
    const float bias2 = b2v[n0 + (n_e & 31)];

    grid_barrier(bid, tid, ++tick);   // zero-init visible everywhere

    int rp = 0;
    for (int t = 0; t < T_; t++) {
        const float* xpt = g_xp + (size_t)t * (B_ * H_);

        // ---- Phase A: h1' = tanh(Xp[t] + h1 @ Wh1) ----
        float xv0 = 0.f, xv1 = 0.f;
        if (tid < NCTA) {                      // prefetch Xp (DRAM) before GEMM
            xv0 = __ldcg(xpt + r_off);
            xv1 = __ldcg(xpt + r_off + H_);
        }
        load_tile(hA_s, g_h1[rp], m0, tid);
        __syncthreads();
        {
            unsigned long long acc[4] = {0ull, 0ull, 0ull, 0ull};
            gemm_acc(hA_s, Wh1_s, w, lane, acc);
            store_red(red_s, w, lane, acc);
        }
        __syncthreads();
        if (tid < NCTA) {
            unsigned long long s = reduce8(red_s, n_e, p_e);
            float lo = tanhf(lo32(s) + xv0);
            float hi = tanhf(hi32(s) + xv1);
            g_h1[rp ^ 1][r_off]      = lo;
            g_h1[rp ^ 1][r_off + H_] = hi;
        }
        grid_barrier(bid, tid, ++tick);

        // ---- Phase B: h2' = tanh(h1' @ Wx2 + h2 @ Wh2 + b2) ----
        load_tile(hA_s, g_h1[rp ^ 1], m0, tid);
        load_tile(hB_s, g_h2[rp],     m0, tid);
        __syncthreads();
        {
            unsigned long long acc[4] = {0ull, 0ull, 0ull, 0ull};
            gemm_acc(hA_s, Wx2_s, w, lane, acc);
            gemm_acc(hB_s, Wh2_s, w, lane, acc);   // same accumulators: one reduction
            store_red(red_s, w, lane, acc);
        }
        __syncthreads();
        if (tid < NCTA) {
            unsigned long long s = reduce8(red_s, n_e, p_e);
            float lo = tanhf(lo32(s) + bias2);
            float hi = tanhf(hi32(s) + bias2);
            g_h2[rp ^ 1][r_off]      = lo;
            g_h2[rp ^ 1][r_off + H_] = hi;
        }
        grid_barrier(bid, tid, ++tick);

        rp ^= 1;
    }
    // T=1024 even: final h2 lives in g_h2[0]
}

// ============================================================================
// Kernel 3: out = softmax(h2_T @ Wd + bd)   (one CTA per batch row)
// ============================================================================
__global__ void __launch_bounds__(128) head_kernel(const float* __restrict__ Wd,
                                                   const float* __restrict__ bd,
                                                   float* __restrict__ out) {
    __shared__ float h_s[H_];
    __shared__ float red[O_];
    const int b = blockIdx.x, o = threadIdx.x;

    const float* h2 = &g_h2[0][b * H_];
    for (int i = o; i < H_; i += O_) h_s[i] = h2[i];
    __syncthreads();

    float acc = bd[o];
#pragma unroll 8
    for (int k = 0; k < H_; k++) acc += h_s[k] * Wd[k * O_ + o];

    red[o] = acc;
    __syncthreads();
    for (int s = 64; s > 0; s >>= 1) {
        if (o < s) red[o] = fmaxf(red[o], red[o + s]);
        __syncthreads();
    }
    const float mx = red[0];
    __syncthreads();
    const float e = expf(acc - mx);
    red[o] = e;
    __syncthreads();
    for (int s = 64; s > 0; s >>= 1) {
        if (o < s) red[o] += red[o + s];
        __syncthreads();
    }
    out[b * O_ + o] = e / red[0];
}

// ============================================================================
extern "C" void kernel_launch(void* const* d_in, const int* in_sizes, int n_in,
                              void* d_out, int out_size) {
    const float* x   = (const float*)d_in[0];
    const float* Wx1 = (const float*)d_in[1];
    const float* Wh1 = (const float*)d_in[2];
    const float* b1  = (const float*)d_in[3];
    const float* Wx2 = (const float*)d_in[4];
    const float* Wh2 = (const float*)d_in[5];
    const float* b2  = (const float*)d_in[6];
    const float* Wd  = (const float*)d_in[7];
    const float* bd  = (const float*)d_in[8];
    float* out = (float*)d_out;

    static bool attr_done = false;
    // cudaFuncSetAttribute is not a stream op; calling it every time is also
    // capture-safe, but cache it to keep replay path clean.
    if (!attr_done) {
        cudaFuncSetAttribute(xproj_kernel,
                             cudaFuncAttributeMaxDynamicSharedMemorySize, 98304);
        cudaFuncSetAttribute(rnn_main_kernel,
                             cudaFuncAttributeMaxDynamicSharedMemorySize, 122880);
        attr_done = true;
    }

    xproj_kernel<<<T_, 256, 98304>>>(x, Wx1, b1);
    rnn_main_kernel<<<NCTA, 256, 122880>>>(Wh1, Wx2, Wh2, b2);
    head_kernel<<<B_, 128>>>(Wd, bd, out);
}

// round 8
// speedup vs baseline: 1.7967x; 1.7967x over previous
#include <cuda_runtime.h>
#include <cstdint>
#include <cstddef>

// Problem constants
#define B_ 128
#define T_ 1024
#define D_ 64
#define H_ 256
#define O_ 128

// 128 CTAs = 16 row-groups (mi) x 8 col-slices (ni); tile = 8 rows x 32 cols.
// Group = 8 CTAs sharing mi; groups are fully independent until the head.
#define NCTA 128
#define GSZ 8
#define BM 8
#define BN 32
#define FPAD 32   // flag padding (ints) = 128B between CTA flags

// ---------------- device globals (static scratch; no runtime allocation) ----
__device__ float g_xp[(size_t)B_ * T_ * H_];   // Xp[t][b][n] = x@Wx1 + b1
__device__ float g_h1[2][B_ * H_];             // double-buffered layer-1 state
__device__ float g_h2[2][B_ * H_];             // double-buffered layer-2 state
__device__ int   g_arrive[NCTA * FPAD];        // barrier flags (monotonic ticks)

// ---------------- packed f32x2 helpers (sm_103a FFMA2 path) ----------------
__device__ __forceinline__ void fma2(unsigned long long& acc,
                                     unsigned long long a,
                                     unsigned long long b) {
    asm("fma.rn.f32x2 %0, %1, %2, %0;" : "+l"(acc) : "l"(a), "l"(b));
}
__device__ __forceinline__ void add2(unsigned long long& acc, unsigned long long a) {
    asm("add.rn.f32x2 %0, %0, %1;" : "+l"(acc) : "l"(a));
}
__device__ __forceinline__ unsigned long long dup2(float v) {
    unsigned long long r;
    asm("mov.b64 %0, {%1, %1};" : "=l"(r) : "r"(__float_as_uint(v)));
    return r;
}
__device__ __forceinline__ float lo32(unsigned long long v) {
    return __uint_as_float((unsigned)(v & 0xffffffffull));
}
__device__ __forceinline__ float hi32(unsigned long long v) {
    return __uint_as_float((unsigned)(v >> 32));
}

// ---------------- fast tanh: MUFU ex2 + rcp, ~1e-6 abs error ---------------
// tanh(x) = 1 - 2/(1 + exp(2x));  exp(2x) = 2^(x * 2*log2(e))
__device__ __forceinline__ float fast_tanh(float x) {
    float e, r;
    asm("ex2.approx.f32 %0, %1;" : "=f"(e) : "f"(x * 2.885390081777927f));
    asm("rcp.approx.f32 %0, %1;" : "=f"(r) : "f"(e + 1.0f));
    return fmaf(-2.0f, r, 1.0f);
}

// ---------------- group barrier: release/acquire flags over 8 CTAs ---------
__device__ __forceinline__ void group_barrier(int gbase, int bid, int tid, int tick) {
    __syncthreads();                       // CTA's stores done + intra-CTA hb
    if (tid == 0) {
        asm volatile("st.release.gpu.global.b32 [%0], %1;"
                     :: "l"(&g_arrive[bid * FPAD]), "r"(tick) : "memory");
    }
    if (tid < GSZ) {                       // thread t polls group-member t's flag
        const int* pf = &g_arrive[(gbase + tid) * FPAD];
        int v;
        do {
            asm volatile("ld.acquire.gpu.global.b32 %0, [%1];"
                         : "=r"(v) : "l"(pf) : "memory");
        } while (v - tick < 0);
    }
    __syncthreads();                       // broadcast acquire to whole CTA
}

// ---------------- load state tile [8 rows, 256 cols] transposed into smem --
// hs layout: hs[k][m], k=0..255, m=0..7
__device__ __forceinline__ void load_tile(float* hs, const float* hg, int m0, int tid) {
    int m  = tid & 7;
    int kq = tid >> 3;   // 0..31
#pragma unroll
    for (int r = 0; r < 2; r++) {
        int k = (kq + r * 32) << 2;
        float4 v = __ldcg((const float4*)(hg + (m0 + m) * H_ + k));
        hs[(k + 0) * 8 + m] = v.x;
        hs[(k + 1) * 8 + m] = v.y;
        hs[(k + 2) * 8 + m] = v.z;
        hs[(k + 3) * 8 + m] = v.w;
    }
}

// ---------------- GEMM partials: weights in registers ----------------------
// Dual: shared hA broadcasts feed both Wh1 (accA) and Wx2 (accB).
__device__ __forceinline__ void gemm_dual(const float* hp,
                                          const float* wa, const float* wb,
                                          unsigned long long accA[4],
                                          unsigned long long accB[4]) {
#pragma unroll
    for (int kk = 0; kk < 32; kk++) {
        ulonglong2 pa = *(const ulonglong2*)(hp + kk * 8);      // rows 0-3 (broadcast)
        ulonglong2 pb = *(const ulonglong2*)(hp + kk * 8 + 4);  // rows 4-7 (broadcast)
        unsigned long long w1 = dup2(wa[kk]);
        fma2(accA[0], pa.x, w1); fma2(accA[1], pa.y, w1);
        fma2(accA[2], pb.x, w1); fma2(accA[3], pb.y, w1);
        unsigned long long w2 = dup2(wb[kk]);
        fma2(accB[0], pa.x, w2); fma2(accB[1], pa.y, w2);
        fma2(accB[2], pb.x, w2); fma2(accB[3], pb.y, w2);
    }
}
__device__ __forceinline__ void gemm_one(const float* hp, const float* wc,
                                         unsigned long long accB[4]) {
#pragma unroll
    for (int kk = 0; kk < 32; kk++) {
        ulonglong2 pa = *(const ulonglong2*)(hp + kk * 8);
        ulonglong2 pb = *(const ulonglong2*)(hp + kk * 8 + 4);
        unsigned long long w3 = dup2(wc[kk]);
        fma2(accB[0], pa.x, w3); fma2(accB[1], pa.y, w3);
        fma2(accB[2], pb.x, w3); fma2(accB[3], pb.y, w3);
    }
}

__device__ __forceinline__ void store_red(unsigned long long* red, int w, int lane,
                                          const unsigned long long acc[4]) {
    ulonglong2* rw = (ulonglong2*)(red + (((w << 5) + lane) << 2));
    rw[0] = make_ulonglong2(acc[0], acc[1]);
    rw[1] = make_ulonglong2(acc[2], acc[3]);
}
__device__ __forceinline__ unsigned long long reduce8(const unsigned long long* red,
                                                      int n_e, int p_e) {
    unsigned long long s = red[(n_e << 2) + p_e];
#pragma unroll
    for (int w2 = 1; w2 < 8; w2++)
        add2(s, red[(((w2 << 5) + n_e) << 2) + p_e]);
    return s;
}

// ============================================================================
// Kernel 1: Xp[t][b][:] = x[b][t][:] @ Wx1 + b1   (fully parallel over t)
// ============================================================================
__global__ void __launch_bounds__(256) xproj_kernel(const float* __restrict__ x,
                                                    const float* __restrict__ Wx1,
                                                    const float* __restrict__ b1) {
    extern __shared__ float sm[];
    float* W_s = sm;            // [64][256]  64KB
    float* x_s = sm + D_ * H_;  // [128][64]  32KB
    const int t = blockIdx.x;
    const int tid = threadIdx.x;

    for (int i = tid; i < D_ * H_; i += 256) W_s[i] = Wx1[i];
    for (int i = tid; i < B_ * D_; i += 256) {
        int b = i >> 6, d = i & 63;
        x_s[i] = x[((size_t)b * T_ + t) * D_ + d];
    }
    __syncthreads();

    float wr[D_];
#pragma unroll
    for (int d = 0; d < D_; d++) wr[d] = W_s[d * H_ + tid];
    const float bv = b1[tid];
    float* op = g_xp + (size_t)t * (B_ * H_) + tid;

    for (int b = 0; b < B_; b++) {
        const float4* xr = (const float4*)(x_s + b * D_);
        float a0 = bv, a1 = 0.f, a2 = 0.f, a3 = 0.f;
#pragma unroll
        for (int d4 = 0; d4 < 16; d4 += 4) {
            float4 v0 = xr[d4 + 0], v1 = xr[d4 + 1], v2 = xr[d4 + 2], v3 = xr[d4 + 3];
            a0 += v0.x * wr[4 * d4 + 0]  + v0.y * wr[4 * d4 + 1]
                + v0.z * wr[4 * d4 + 2]  + v0.w * wr[4 * d4 + 3];
            a1 += v1.x * wr[4 * d4 + 4]  + v1.y * wr[4 * d4 + 5]
                + v1.z * wr[4 * d4 + 6]  + v1.w * wr[4 * d4 + 7];
            a2 += v2.x * wr[4 * d4 + 8]  + v2.y * wr[4 * d4 + 9]
                + v2.z * wr[4 * d4 + 10] + v2.w * wr[4 * d4 + 11];
            a3 += v3.x * wr[4 * d4 + 12] + v3.y * wr[4 * d4 + 13]
                + v3.z * wr[4 * d4 + 14] + v3.w * wr[4 * d4 + 15];
        }
        op[(size_t)b * H_] = (a0 + a1) + (a2 + a3);
    }
}

// ============================================================================
// Kernel 2: persistent pipelined scan — ONE barrier/step over 8-CTA groups.
// Phase p: h1(p+1) = tanh(Xp[p] + h1(p)@Wh1)          [p < T]
//          h2(p)   = tanh(h1(p)@Wx2 + h2(p-1)@Wh2+b2) [p >= 1]
// ============================================================================
__global__ void __launch_bounds__(256) rnn_main_kernel(const float* __restrict__ Wh1,
                                                       const float* __restrict__ Wx2,
                                                       const float* __restrict__ Wh2,
                                                       const float* __restrict__ b2v) {
    extern __shared__ float smem[];
    float* hA_s = smem;                                          // [256][8] 8KB
    float* hB_s = smem + 2048;                                   // [256][8] 8KB
    unsigned long long* redA = (unsigned long long*)(smem + 4096); // 8KB
    unsigned long long* redB = (unsigned long long*)(smem + 6144); // 8KB

    const int bid = blockIdx.x;
    const int tid = threadIdx.x;
    const int w = tid >> 5, lane = tid & 31;
    const int mi = bid >> 3, ni = bid & 7;
    const int m0 = mi * BM, n0 = ni * BN;
    const int gbase = bid & ~(GSZ - 1);

    // Weight slices live in registers for the whole scan (constant).
    float wh1r[32], wx2r[32], wh2r[32];
    {
        const int col = n0 + lane;
#pragma unroll
        for (int kk = 0; kk < 32; kk++) {
            int k = (w << 5) + kk;
            wh1r[kk] = Wh1[k * H_ + col];
            wx2r[kk] = Wx2[k * H_ + col];
            wh2r[kk] = Wh2[k * H_ + col];
        }
    }

    // Zero-init h1(0), h2(0) (each CTA zeros its own 8x32 slice of both)
    {
        int m = tid >> 5, n = tid & 31;
        g_h1[0][(m0 + m) * H_ + n0 + n] = 0.f;
        g_h2[0][(m0 + m) * H_ + n0 + n] = 0.f;
    }

    // Launch-relative tick base (flags never reset; uniform across launches)
    int tick = g_arrive[bid * FPAD];

    // Epilogue mapping: e_tid in [0,128) -> rows (m0+2p_e, +1), col n0+n_e
    const int e_tid = tid & 127;
    const int n_e = e_tid >> 2;
    const int p_e = e_tid & 3;
    const int r_off = (m0 + 2 * p_e) * H_ + n0 + n_e;
    const float bias2 = b2v[n0 + n_e];

    group_barrier(gbase, bid, tid, ++tick);   // zero-init visible in group

    for (int p = 0; p <= T_; p++) {
        const int rp = p & 1;     // h1 read buf (holds h1(p)); h2 write buf
        // h1 write buf = rp^1;  h2 read buf (h2(p-1)) = rp^1

        float xv0 = 0.f, xv1 = 0.f;
        if (tid < 128 && p < T_) {            // prefetch Xp[p] early (DRAM)
            const float* xpt = g_xp + (size_t)p * (B_ * H_);
            xv0 = __ldcg(xpt + r_off);
            xv1 = __ldcg(xpt + r_off + H_);
        }
        load_tile(hA_s, g_h1[rp], m0, tid);
        if (p >= 1) load_tile(hB_s, g_h2[rp ^ 1], m0, tid);
        __syncthreads();

        unsigned long long accA[4] = {0ull, 0ull, 0ull, 0ull};
        unsigned long long accB[4] = {0ull, 0ull, 0ull, 0ull};
        const float* hpA = hA_s + (w << 5) * 8;
        const float* hpB = hB_s + (w << 5) * 8;
        gemm_dual(hpA, wh1r, wx2r, accA, accB);   // h1@Wh1 -> accA, h1@Wx2 -> accB
        gemm_one(hpB, wh2r, accB);                // + h2@Wh2 -> accB
        store_red(redA, w, lane, accA);
        store_red(redB, w, lane, accB);
        __syncthreads();

        if (tid < 128) {
            if (p < T_) {                     // h1(p+1) epilogue
                unsigned long long s = reduce8(redA, n_e, p_e);
                g_h1[rp ^ 1][r_off]      = fast_tanh(lo32(s) + xv0);
                g_h1[rp ^ 1][r_off + H_] = fast_tanh(hi32(s) + xv1);
            }
        } else {
            if (p >= 1) {                     // h2(p) epilogue
                unsigned long long s = reduce8(redB, n_e, p_e);
                g_h2[rp][r_off]      = fast_tanh(lo32(s) + bias2);
                g_h2[rp][r_off + H_] = fast_tanh(hi32(s) + bias2);
            }
        }
        group_barrier(gbase, bid, tid, ++tick);
    }
    // h2(1024) lives in g_h2[0] (1024 & 1 == 0)
}

// ============================================================================
// Kernel 3: out = softmax(h2_T @ Wd + bd)   (one CTA per batch row)
// ============================================================================
__global__ void __launch_bounds__(128) head_kernel(const float* __restrict__ Wd,
                                                   const float* __restrict__ bd,
                                                   float* __restrict__ out) {
    __shared__ float h_s[H_];
    __shared__ float red[O_];
    const int b = blockIdx.x, o = threadIdx.x;

    const float* h2 = &g_h2[0][b * H_];
    for (int i = o; i < H_; i += O_) h_s[i] = h2[i];
    __syncthreads();

    float acc = bd[o];
#pragma unroll 8
    for (int k = 0; k < H_; k++) acc += h_s[k] * Wd[k * O_ + o];

    red[o] = acc;
    __syncthreads();
    for (int s = 64; s > 0; s >>= 1) {
        if (o < s) red[o] = fmaxf(red[o], red[o + s]);
        __syncthreads();
    }
    const float mx = red[0];
    __syncthreads();
    const float e = expf(acc - mx);
    red[o] = e;
    __syncthreads();
    for (int s = 64; s > 0; s >>= 1) {
        if (o < s) red[o] += red[o + s];
        __syncthreads();
    }
    out[b * O_ + o] = e / red[0];
}

// ============================================================================
extern "C" void kernel_launch(void* const* d_in, const int* in_sizes, int n_in,
                              void* d_out, int out_size) {
    const float* x   = (const float*)d_in[0];
    const float* Wx1 = (const float*)d_in[1];
    const float* Wh1 = (const float*)d_in[2];
    const float* b1  = (const float*)d_in[3];
    const float* Wx2 = (const float*)d_in[4];
    const float* Wh2 = (const float*)d_in[5];
    const float* b2  = (const float*)d_in[6];
    const float* Wd  = (const float*)d_in[7];
    const float* bd  = (const float*)d_in[8];
    float* out = (float*)d_out;

    static bool attr_done = false;
    if (!attr_done) {
        cudaFuncSetAttribute(xproj_kernel,
                             cudaFuncAttributeMaxDynamicSharedMemorySize, 98304);
        // Over-allocate rnn smem to guarantee 1 CTA/SM (single-wave residency)
        cudaFuncSetAttribute(rnn_main_kernel,
                             cudaFuncAttributeMaxDynamicSharedMemorySize, 102400);
        attr_done = true;
    }

    xproj_kernel<<<T_, 256, 98304>>>(x, Wx1, b1);
    rnn_main_kernel<<<NCTA, 256, 102400>>>(Wh1, Wx2, Wh2, b2);
    head_kernel<<<B_, 128>>>(Wd, bd, out);
}

// round 10
// speedup vs baseline: 1.8394x; 1.0238x over previous
#include <cuda_runtime.h>
#include <cstdint>
#include <cstddef>

// Problem constants
#define B_ 128
#define T_ 1024
#define D_ 64
#define H_ 256
#define O_ 128

// 128 CTAs = 16 clusters of 8; cluster = row-group (8 batch rows), rank = col-slice
#define NCTA 128
#define CSZ 8
#define BM 8
#define BN 32

// Dynamic-smem byte offsets (state buffers are [256][8] floats = 8KB each)
#define OFF_HA0  0u          // h1 state, parity 0
#define OFF_HA1  8192u       // h1 state, parity 1
#define OFF_HB0  16384u      // h2 state, parity 0
#define OFF_HB1  24576u      // h2 state, parity 1
#define OFF_REDA 32768u      // reduction scratch (u64), 8KB
#define OFF_REDB 40960u
#define SMEM_REQ 102400      // over-request -> 1 CTA/SM guaranteed

// ---------------- device globals (static scratch; no runtime allocation) ----
__device__ float g_xp[(size_t)B_ * T_ * H_];   // Xp[t][b][n] = x@Wx1 + b1
__device__ float g_h2f[B_ * H_];               // final h2(T) for the head

// ---------------- packed f32x2 helpers -------------------------------------
__device__ __forceinline__ void fma2(unsigned long long& acc,
                                     unsigned long long a,
                                     unsigned long long b) {
    asm("fma.rn.f32x2 %0, %1, %2, %0;" : "+l"(acc) : "l"(a), "l"(b));
}
__device__ __forceinline__ void add2(unsigned long long& acc, unsigned long long a) {
    asm("add.rn.f32x2 %0, %0, %1;" : "+l"(acc) : "l"(a));
}
__device__ __forceinline__ unsigned long long dup2(float v) {
    unsigned long long r;
    asm("mov.b64 %0, {%1, %1};" : "=l"(r) : "r"(__float_as_uint(v)));
    return r;
}
__device__ __forceinline__ unsigned long long pack2(float lo, float hi) {
    unsigned long long r;
    asm("mov.b64 %0, {%1, %2};" : "=l"(r) : "r"(__float_as_uint(lo)), "r"(__float_as_uint(hi)));
    return r;
}
__device__ __forceinline__ float lo32(unsigned long long v) {
    return __uint_as_float((unsigned)(v & 0xffffffffull));
}
__device__ __forceinline__ float hi32(unsigned long long v) {
    return __uint_as_float((unsigned)(v >> 32));
}

// ---------------- fast tanh: MUFU ex2 + rcp, ~1e-6 abs error ---------------
__device__ __forceinline__ float fast_tanh(float x) {
    float e, r;
    asm("ex2.approx.f32 %0, %1;" : "=f"(e) : "f"(x * 2.885390081777927f));
    asm("rcp.approx.f32 %0, %1;" : "=f"(r) : "f"(e + 1.0f));
    return fmaf(-2.0f, r, 1.0f);
}

// ---------------- cluster primitives ---------------------------------------
__device__ __forceinline__ uint32_t smem_u32(const void* p) {
    uint32_t a;
    asm("{ .reg .u64 t; cvta.to.shared.u64 t, %1; cvt.u32.u64 %0, t; }" : "=r"(a) : "l"(p));
    return a;
}
__device__ __forceinline__ uint32_t mapa_rank(uint32_t local, uint32_t rank) {
    uint32_t r;
    asm("mapa.shared::cluster.u32 %0, %1, %2;" : "=r"(r) : "r"(local), "r"(rank));
    return r;
}
__device__ __forceinline__ void st_cluster_u64(uint32_t addr, unsigned long long v) {
    asm volatile("st.shared::cluster.u64 [%0], %1;" :: "r"(addr), "l"(v) : "memory");
}
// HW cluster barrier: release on arrive, acquire on wait (orders DSMEM stores)
#define CLUSTER_SYNC() do { \
    asm volatile("barrier.cluster.arrive.aligned;" ::: "memory"); \
    asm volatile("barrier.cluster.wait.aligned;" ::: "memory"); } while (0)

// ---------------- GEMM partials: weights in registers ----------------------
__device__ __forceinline__ void gemm_dual(const float* hp,
                                          const float* wa, const float* wb,
                                          unsigned long long accA[4],
                                          unsigned long long accB[4]) {
#pragma unroll
    for (int kk = 0; kk < 32; kk++) {
        ulonglong2 pa = *(const ulonglong2*)(hp + kk * 8);      // rows 0-3 (bcast)
        ulonglong2 pb = *(const ulonglong2*)(hp + kk * 8 + 4);  // rows 4-7 (bcast)
        unsigned long long w1 = dup2(wa[kk]);
        fma2(accA[0], pa.x, w1); fma2(accA[1], pa.y, w1);
        fma2(accA[2], pb.x, w1); fma2(accA[3], pb.y, w1);
        unsigned long long w2 = dup2(wb[kk]);
        fma2(accB[0], pa.x, w2); fma2(accB[1], pa.y, w2);
        fma2(accB[2], pb.x, w2); fma2(accB[3], pb.y, w2);
    }
}
__device__ __forceinline__ void gemm_one(const float* hp, const float* wc,
                                         unsigned long long accB[4]) {
#pragma unroll
    for (int kk = 0; kk < 32; kk++) {
        ulonglong2 pa = *(const ulonglong2*)(hp + kk * 8);
        ulonglong2 pb = *(const ulonglong2*)(hp + kk * 8 + 4);
        unsigned long long w3 = dup2(wc[kk]);
        fma2(accB[0], pa.x, w3); fma2(accB[1], pa.y, w3);
        fma2(accB[2], pb.x, w3); fma2(accB[3], pb.y, w3);
    }
}
__device__ __forceinline__ void store_red(unsigned long long* red, int w, int lane,
                                          const unsigned long long acc[4]) {
    ulonglong2* rw = (ulonglong2*)(red + (((w << 5) + lane) << 2));
    rw[0] = make_ulonglong2(acc[0], acc[1]);
    rw[1] = make_ulonglong2(acc[2], acc[3]);
}
__device__ __forceinline__ unsigned long long reduce8(const unsigned long long* red,
                                                      int n_e, int p_e) {
    unsigned long long s = red[(n_e << 2) + p_e];
#pragma unroll
    for (int w2 = 1; w2 < 8; w2++)
        add2(s, red[(((w2 << 5) + n_e) << 2) + p_e]);
    return s;
}

// ============================================================================
// Kernel 1: Xp[t][b][:] = x[b][t][:] @ Wx1 + b1   (fully parallel over t)
// ============================================================================
__global__ void __launch_bounds__(256) xproj_kernel(const float* __restrict__ x,
                                                    const float* __restrict__ Wx1,
                                                    const float* __restrict__ b1) {
    extern __shared__ float sm[];
    float* W_s = sm;            // [64][256]  64KB
    float* x_s = sm + D_ * H_;  // [128][64]  32KB
    const int t = blockIdx.x;
    const int tid = threadIdx.x;

    for (int i = tid; i < D_ * H_; i += 256) W_s[i] = Wx1[i];
    for (int i = tid; i < B_ * D_; i += 256) {
        int b = i >> 6, d = i & 63;
        x_s[i] = x[((size_t)b * T_ + t) * D_ + d];
    }
    __syncthreads();

    float wr[D_];
#pragma unroll
    for (int d = 0; d < D_; d++) wr[d] = W_s[d * H_ + tid];
    const float bv = b1[tid];
    float* op = g_xp + (size_t)t * (B_ * H_) + tid;

    for (int b = 0; b < B_; b++) {
        const float4* xr = (const float4*)(x_s + b * D_);
        float a0 = bv, a1 = 0.f, a2 = 0.f, a3 = 0.f;
#pragma unroll
        for (int d4 = 0; d4 < 16; d4 += 4) {
            float4 v0 = xr[d4 + 0], v1 = xr[d4 + 1], v2 = xr[d4 + 2], v3 = xr[d4 + 3];
            a0 += v0.x * wr[4 * d4 + 0]  + v0.y * wr[4 * d4 + 1]
                + v0.z * wr[4 * d4 + 2]  + v0.w * wr[4 * d4 + 3];
            a1 += v1.x * wr[4 * d4 + 4]  + v1.y * wr[4 * d4 + 5]
                + v1.z * wr[4 * d4 + 6]  + v1.w * wr[4 * d4 + 7];
            a2 += v2.x * wr[4 * d4 + 8]  + v2.y * wr[4 * d4 + 9]
                + v2.z * wr[4 * d4 + 10] + v2.w * wr[4 * d4 + 11];
            a3 += v3.x * wr[4 * d4 + 12] + v3.y * wr[4 * d4 + 13]
                + v3.z * wr[4 * d4 + 14] + v3.w * wr[4 * d4 + 15];
        }
        op[(size_t)b * H_] = (a0 + a1) + (a2 + a3);
    }
}

// ============================================================================
// Kernel 2: persistent scan — DSMEM all-gather inside 8-CTA clusters,
// ONE hardware cluster barrier per phase (race-free with double buffering).
// Phase p: h1(p+1) = tanh(Xp[p] + h1(p)@Wh1)            [p < T]
//          h2(p)   = tanh(h1(p)@Wx2 + h2(p-1)@Wh2 + b2) [p >= 1]
// Producer rank r writes its cols [32r,32r+32) (== consumers' k-chunk r),
// already transposed to GEMM layout, into every peer's parity-(q^1) buffer.
// ============================================================================
__global__ void __launch_bounds__(256, 1) __cluster_dims__(CSZ, 1, 1)
rnn_main_kernel(const float* __restrict__ Wh1,
                const float* __restrict__ Wx2,
                const float* __restrict__ Wh2,
                const float* __restrict__ b2v) {
    extern __shared__ char smem[];
    const uint32_t sbase = smem_u32(smem);
    unsigned long long* redA = (unsigned long long*)(smem + OFF_REDA);
    unsigned long long* redB = (unsigned long long*)(smem + OFF_REDB);

    const int tid = threadIdx.x;
    const int w = tid >> 5, lane = tid & 31;
    uint32_t rank;
    asm("mov.u32 %0, %%cluster_ctarank;" : "=r"(rank));
    const int mi = blockIdx.x >> 3;
    const int m0 = mi * BM, n0 = (int)rank * BN;

    // Weight slices live in registers for the whole scan
    float wh1r[32], wx2r[32], wh2r[32];
    {
        const int col = n0 + lane;
#pragma unroll
        for (int kk = 0; kk < 32; kk++) {
            int k = (w << 5) + kk;
            wh1r[kk] = Wh1[k * H_ + col];
            wx2r[kk] = Wx2[k * H_ + col];
            wh2r[kk] = Wh2[k * H_ + col];
        }
    }

    // Zero all four local state buffers (phase-0 inputs + h2(0) for phase 1)
    {
        float* s0 = (float*)(smem + OFF_HA0);
        for (int i = tid; i < 8192; i += 256) s0[i] = 0.f;   // HA0..HB1 contiguous
    }

    // Peer smem bases (constant-index unrolled -> registers)
    uint32_t pb[8];
#pragma unroll
    for (int r = 0; r < 8; r++) pb[r] = mapa_rank(sbase, (uint32_t)r);

    CLUSTER_SYNC();   // zero-init visible cluster-wide

    // Epilogue mapping: e in [0,128) -> rows (m0+2p_e, +1), col n0+n_e
    const int e = tid & 127;
    const int n_e = e >> 2;
    const int p_e = e & 3;
    const int r_off = (m0 + 2 * p_e) * H_ + n0 + n_e;
    const float bias2 = b2v[n0 + n_e];
    const uint32_t soff = (uint32_t)((n0 + n_e) * 32 + p_e * 8);  // byte off in state buf

    for (int p = 0; p <= T_; p++) {
        const int q = p & 1;   // input-buffer parity

        // Prefetch Xp[p] immediately (DRAM latency hides under the GEMM)
        float xv0 = 0.f, xv1 = 0.f;
        if (tid < 128 && p < T_) {
            const float* xpt = g_xp + (size_t)p * (B_ * H_);
            xv0 = __ldcg(xpt + r_off);
            xv1 = __ldcg(xpt + r_off + H_);
        }

        const float* hAr = (const float*)(smem + (q ? OFF_HA1 : OFF_HA0)) + (w << 5) * 8;
        const float* hBr = (const float*)(smem + (q ? OFF_HB1 : OFF_HB0)) + (w << 5) * 8;

        unsigned long long accA[4] = {0ull, 0ull, 0ull, 0ull};
        unsigned long long accB[4] = {0ull, 0ull, 0ull, 0ull};
        gemm_dual(hAr, wh1r, wx2r, accA, accB);   // h1@Wh1 -> accA, h1@Wx2 -> accB
        gemm_one(hBr, wh2r, accB);                // + h2@Wh2 -> accB
        store_red(redA, w, lane, accA);
        store_red(redB, w, lane, accB);
        __syncthreads();

        const uint32_t dHA = (q ? OFF_HA0 : OFF_HA1) + soff;   // dest parity q^1
        const uint32_t dHB = (q ? OFF_HB0 : OFF_HB1) + soff;

        if (tid < 128) {
            if (p < T_) {                          // h1(p+1): broadcast to all 8 peers
                unsigned long long s = reduce8(redA, n_e, p_e);
                unsigned long long v = pack2(fast_tanh(lo32(s) + xv0),
                                             fast_tanh(hi32(s) + xv1));
#pragma unroll
                for (int r = 0; r < 8; r++) st_cluster_u64(pb[r] + dHA, v);
            }
        } else {
            if (p >= 1) {                          // h2(p)
                unsigned long long s = reduce8(redB, n_e, p_e);
                float lo = fast_tanh(lo32(s) + bias2);
                float hi = fast_tanh(hi32(s) + bias2);
                if (p == T_) {                     // final state -> global for head
                    g_h2f[r_off]      = lo;
                    g_h2f[r_off + H_] = hi;
                } else {
                    unsigned long long v = pack2(lo, hi);
#pragma unroll
                    for (int r = 0; r < 8; r++) st_cluster_u64(pb[r] + dHB, v);
                }
            }
        }

        // One HW cluster barrier per phase: orders all DSMEM stores (release/
        // acquire at cluster scope) and protects red/state buffers for reuse.
        CLUSTER_SYNC();
    }
}

// ============================================================================
// Kernel 3: out = softmax(h2_T @ Wd + bd)   (one CTA per batch row)
// ============================================================================
__global__ void __launch_bounds__(128) head_kernel(const float* __restrict__ Wd,
                                                   const float* __restrict__ bd,
                                                   float* __restrict__ out) {
    __shared__ float h_s[H_];
    __shared__ float red[O_];
    const int b = blockIdx.x, o = threadIdx.x;

    const float* h2 = &g_h2f[b * H_];
    for (int i = o; i < H_; i += O_) h_s[i] = h2[i];
    __syncthreads();

    float acc = bd[o];
#pragma unroll 8
    for (int k = 0; k < H_; k++) acc += h_s[k] * Wd[k * O_ + o];

    red[o] = acc;
    __syncthreads();
    for (int s = 64; s > 0; s >>= 1) {
        if (o < s) red[o] = fmaxf(red[o], red[o + s]);
        __syncthreads();
    }
    const float mx = red[0];
    __syncthreads();
    const float e = expf(acc - mx);
    red[o] = e;
    __syncthreads();
    for (int s = 64; s > 0; s >>= 1) {
        if (o < s) red[o] += red[o + s];
        __syncthreads();
    }
    out[b * O_ + o] = e / red[0];
}

// ============================================================================
extern "C" void kernel_launch(void* const* d_in, const int* in_sizes, int n_in,
                              void* d_out, int out_size) {
    const float* x   = (const float*)d_in[0];
    const float* Wx1 = (const float*)d_in[1];
    const float* Wh1 = (const float*)d_in[2];
    const float* b1  = (const float*)d_in[3];
    const float* Wx2 = (const float*)d_in[4];
    const float* Wh2 = (const float*)d_in[5];
    const float* b2  = (const float*)d_in[6];
    const float* Wd  = (const float*)d_in[7];
    const float* bd  = (const float*)d_in[8];
    float* out = (float*)d_out;

    static bool attr_done = false;
    if (!attr_done) {
        cudaFuncSetAttribute(xproj_kernel,
                             cudaFuncAttributeMaxDynamicSharedMemorySize, 98304);
        cudaFuncSetAttribute(rnn_main_kernel,
                             cudaFuncAttributeMaxDynamicSharedMemorySize, SMEM_REQ);
        attr_done = true;
    }

    xproj_kernel<<<T_, 256, 98304>>>(x, Wx1, b1);
    rnn_main_kernel<<<NCTA, 256, SMEM_REQ>>>(Wh1, Wx2, Wh2, b2);  // cluster dims baked
    head_kernel<<<B_, 128>>>(Wd, bd, out);
}